// round 3
// baseline (speedup 1.0000x reference)
#include <cuda_runtime.h>

#define T_SEQ 2048
#define B_SZ  512

typedef unsigned long long u64;

// ---------- packed f32x2 helpers ----------
__device__ __forceinline__ u64 pack2(float a, float b) {
    u64 d; asm("mov.b64 %0,{%1,%2};" : "=l"(d) : "f"(a), "f"(b)); return d;
}
__device__ __forceinline__ void unpack2(u64 v, float& a, float& b) {
    asm("mov.b64 {%0,%1},%2;" : "=f"(a), "=f"(b) : "l"(v));
}
__device__ __forceinline__ u64 fma2(u64 a, u64 b, u64 c) {
    u64 d; asm("fma.rn.f32x2 %0,%1,%2,%3;" : "=l"(d) : "l"(a), "l"(b), "l"(c)); return d;
}

// ---------- fast activations (MUFU ex2/rcp, ~1e-6 err — validated R1/R2) ----------
__device__ __forceinline__ float ex2f(float x) { float y; asm("ex2.approx.ftz.f32 %0,%1;" : "=f"(y) : "f"(x)); return y; }
__device__ __forceinline__ float rcpf(float x) { float y; asm("rcp.approx.ftz.f32 %0,%1;" : "=f"(y) : "f"(x)); return y; }
__device__ __forceinline__ float sigm(float x)  { return rcpf(1.f + ex2f(-1.4426950408889634f * x)); }
__device__ __forceinline__ float tanhf_(float x){ float e = ex2f(2.8853900817779268f * x); return 1.f - 2.f * rcpf(e + 1.f); }

// per-element (trio) barrier: 3 warps = 96 threads, barrier id = e+1
#define TRIO_BAR(id) asm volatile("bar.sync %0, 96;" :: "r"(id) : "memory")

// =====================================================================
// Fully fused 2-layer LSTM + dense head. One persistent kernel.
// 3 specialized warps per batch element (trio):
//   role 0: layer-0 cell              (h0[t] at tick n = t)
//   role 1: input projection layer-1  (xp1[t] at tick n = t+1)
//   role 2: layer-1 cell + dense head (out[t] at tick n = t+2)
// Block = 4 elements x 3 roles = 12 warps.
//   e = wid/3, role = wid%3  ->  SMSP (wid%4) hosts warps of DIFFERENT
//   trios and roles, and per-trio named barriers let trios drift, so
//   one trio's FMA burst hides another's activation tail / barrier wait.
// =====================================================================
__global__ void __launch_bounds__(384, 1)
k_fused(const float* __restrict__ x,
        const float* __restrict__ Wih0, const float* __restrict__ Whh0,
        const float* __restrict__ bih0, const float* __restrict__ bhh0,
        const float* __restrict__ Wih1, const float* __restrict__ Whh1,
        const float* __restrict__ bih1, const float* __restrict__ bhh1,
        const float* __restrict__ Wd,   const float* __restrict__ bd,
        float* __restrict__ out)
{
    __shared__ __align__(16) float h0ring[4][2][64];   // duplicated {h,h} pairs
    __shared__ __align__(16) u64   pring[4][2][64];    // [j]={i,f}, [32+j]={g,o}
    __shared__ __align__(16) float h1buf[4][64];       // duplicated {h,h} pairs

    const int tid  = threadIdx.x;
    const int wid  = tid >> 5, j = tid & 31;
    const int e    = wid / 3;          // element slot in block (0..3)
    const int role = wid - 3 * e;      // 0=L0 cell, 1=proj, 2=L1 cell+head
    const int b    = blockIdx.x * 4 + e;
    const int bar  = e + 1;            // named barrier id for this trio

    // zero initial hidden states
    for (int i = tid; i < 4 * 2 * 64; i += 384) ((float*)h0ring)[i] = 0.f;
    for (int i = tid; i < 4 * 64;     i += 384) ((float*)h1buf)[i]  = 0.f;

    // per-role weight matrix -> 64 u64 regs of gate-pair columns
    const float* Wsrc = (role == 0) ? Whh0 : (role == 1) ? Wih1 : Whh1;
    u64 w_if[32], w_go[32];
#pragma unroll
    for (int k = 0; k < 32; k++) {
        w_if[k] = pack2(Wsrc[j * 32 + k],        Wsrc[(32 + j) * 32 + k]);
        w_go[k] = pack2(Wsrc[(64 + j) * 32 + k], Wsrc[(96 + j) * 32 + k]);
    }

    u64 wx_if = 0, wx_go = 0, bs_if = 0, bs_go = 0;
    if (role == 0) {
        wx_if = pack2(Wih0[j],      Wih0[32 + j]);
        wx_go = pack2(Wih0[64 + j], Wih0[96 + j]);
        bs_if = pack2(bih0[j] + bhh0[j],           bih0[32 + j] + bhh0[32 + j]);
        bs_go = pack2(bih0[64 + j] + bhh0[64 + j], bih0[96 + j] + bhh0[96 + j]);
    } else if (role == 1) {
        bs_if = pack2(bih1[j] + bhh1[j],           bih1[32 + j] + bhh1[32 + j]);
        bs_go = pack2(bih1[64 + j] + bhh1[64 + j], bih1[96 + j] + bhh1[96 + j]);
    }
    const float wd  = Wd[j];
    const float bdv = bd[0];

    float c  = 0.f;                    // cell state (roles 0 and 2)
    float xt = x[b];                   // x[t=0]  (IN == 1)

    __syncthreads();                   // init visible to all trios

#pragma unroll 1
    for (int n = 0; n < T_SEQ + 2; n++) {
        if (role == 0) {
            if (n < T_SEQ) {
                float xn = (n + 1 < T_SEQ) ? x[(n + 1) * B_SZ + b] : 0.f;
                u64 xs  = pack2(xt, xt);
                u64 aif = fma2(xs, wx_if, bs_if);
                u64 ago = fma2(xs, wx_go, bs_go);
                const u64* hv = reinterpret_cast<const u64*>(h0ring[e][(n + 1) & 1]); // (n-1)&1
#pragma unroll
                for (int k = 0; k < 32; k++) {
                    u64 h2 = hv[k];
                    aif = fma2(h2, w_if[k], aif);
                    ago = fma2(h2, w_go[k], ago);
                }
                float gi, gf, gg, go;
                unpack2(aif, gi, gf); unpack2(ago, gg, go);
                gi = sigm(gi); gf = sigm(gf); gg = tanhf_(gg); go = sigm(go);
                c = gf * c + gi * gg;
                float h = go * tanhf_(c);
                reinterpret_cast<u64*>(h0ring[e][n & 1])[j] = pack2(h, h);
                xt = xn;
            }
        } else if (role == 1) {
            if (n >= 1 && n <= T_SEQ) {
                const u64* hv = reinterpret_cast<const u64*>(h0ring[e][(n - 1) & 1]);
                u64 aif = bs_if, ago = bs_go;
#pragma unroll
                for (int k = 0; k < 32; k++) {
                    u64 h2 = hv[k];
                    aif = fma2(h2, w_if[k], aif);
                    ago = fma2(h2, w_go[k], ago);
                }
                pring[e][(n - 1) & 1][j]      = aif;
                pring[e][(n - 1) & 1][32 + j] = ago;
            }
        } else {
            if (n >= 2) {
                const int t = n - 2;
                const u64* pv = pring[e][n & 1];      // slot (n-2)&1 == n&1
                u64 aif = pv[j];
                u64 ago = pv[32 + j];
                const u64* hv = reinterpret_cast<const u64*>(h1buf[e]);
#pragma unroll
                for (int k = 0; k < 32; k++) {
                    u64 h2 = hv[k];
                    aif = fma2(h2, w_if[k], aif);
                    ago = fma2(h2, w_go[k], ago);
                }
                __syncwarp();   // all lanes done reading h1buf before overwrite
                float gi, gf, gg, go;
                unpack2(aif, gi, gf); unpack2(ago, gg, go);
                gi = sigm(gi); gf = sigm(gf); gg = tanhf_(gg); go = sigm(go);
                c = gf * c + gi * gg;
                float h = go * tanhf_(c);
                reinterpret_cast<u64*>(h1buf[e])[j] = pack2(h, h);

                // fused dense head (off the recurrence chain, hideable tail)
                float y = h * wd;
#pragma unroll
                for (int off = 16; off > 0; off >>= 1)
                    y += __shfl_xor_sync(0xffffffffu, y, off);
                if (j == 0) out[t * B_SZ + b] = y + bdv;
            }
        }
        TRIO_BAR(bar);                 // only this element's 3 warps sync
    }
}

// =====================================================================
extern "C" void kernel_launch(void* const* d_in, const int* in_sizes, int n_in,
                              void* d_out, int out_size)
{
    const float* x    = (const float*)d_in[0];
    const float* Wih0 = (const float*)d_in[1];
    const float* Whh0 = (const float*)d_in[2];
    const float* bih0 = (const float*)d_in[3];
    const float* bhh0 = (const float*)d_in[4];
    const float* Wih1 = (const float*)d_in[5];
    const float* Whh1 = (const float*)d_in[6];
    const float* bih1 = (const float*)d_in[7];
    const float* bhh1 = (const float*)d_in[8];
    const float* Wd   = (const float*)d_in[9];
    const float* bd   = (const float*)d_in[10];

    k_fused<<<128, 384>>>(x, Wih0, Whh0, bih0, bhh0,
                          Wih1, Whh1, bih1, bhh1, Wd, bd, (float*)d_out);
}